// round 7
// baseline (speedup 1.0000x reference)
#include <cuda_runtime.h>
#include <math.h>

#define NCELL 512
#define C 32
#define NREP 32           // counter replicas per cell (replica = point_idx & 31)
#define CAP32 64          // slots per (cell, replica); mean ~30.5
#define HREP 16           // replicas handled per scatter CTA
#define SCAP_H 768        // smem record cap per half-bin; mean ~488, +12 sigma

// -------- static scratch (no cudaMalloc allowed) --------
__device__ int   g_cnt32[NCELL * NREP];
__device__ int4  g_rec32[NCELL * NREP * CAP32];   // {idx, fx, fy, fz}
__device__ float g_img[NCELL * C];
__device__ float g_h1 [NCELL * C];
__device__ float g_t  [NCELL * C];
__device__ float g_h2 [NCELL * C];
__device__ float g_out[NCELL * C];
__device__ float g_B  [NCELL * C];
__device__ int   g_pad[32];

// -------- zero counters + accumulated buffers --------
__global__ void zero_k() {
    int j = blockIdx.x * 256 + threadIdx.x;          // 16384 threads
    g_cnt32[j] = 0;
    g_img[j] = 0.f; g_h1[j] = 0.f; g_t[j] = 0.f; g_out[j] = 0.f;
}

// -------- bin points: replicated counters kill atomic serialization --------
__global__ void bin_k(const float* __restrict__ pos, int N) {
    int p = blockIdx.x * 256 + threadIdx.x;
    if (p >= N) return;
    float sx = pos[3 * p + 0] * 8.f;
    float sy = pos[3 * p + 1] * 8.f;
    float sz = pos[3 * p + 2] * 8.f;
    float bx = floorf(sx), by = floorf(sy), bz = floorf(sz);
    int cell = ((((int)bx) & 7) << 6) | ((((int)by) & 7) << 3) | (((int)bz) & 7);
    int r = p & (NREP - 1);
    int slot = atomicAdd(&g_cnt32[cell * NREP + r], 1);
    if (slot < CAP32) {
        int4 rec;
        rec.x = p;
        rec.y = __float_as_int(sx - bx);
        rec.z = __float_as_int(sy - by);
        rec.w = __float_as_int(sz - bz);
        g_rec32[(cell * NREP + r) * CAP32 + slot] = rec;
    }
}

// -------- probe: keeps scatter_k in ncu's profiled slot (4th launch) --------
__global__ void probe_k() {
    if (threadIdx.x == 0) g_pad[0] = 1;
}

#define ACC(rc, fc) { \
    float fx = __int_as_float((rc).y), fy = __int_as_float((rc).z), fz = __int_as_float((rc).w); \
    float gx = 1.f - fx, gy = 1.f - fy, gz = 1.f - fz; \
    float w00 = gy * gz, w01 = gy * fz, w10 = fy * gz, w11 = fy * fz; \
    float p0 = gx * (fc), p1 = fx * (fc); \
    a0 += w00 * p0; a1 += w01 * p0; a2 += w10 * p0; a3 += w11 * p0; \
    a4 += w00 * p1; a5 += w01 * p1; a6 += w10 * p1; a7 += w11 * p1; }

// -------- scatter: 2 CTAs per bin (replica halves), smem-staged records,
//          8-deep feat load ring per warp --------
__global__ void __launch_bounds__(256) scatter_k(const float* __restrict__ feat) {
    __shared__ int4  s_rec[SCAP_H];
    __shared__ int   s_pref[HREP + 1];
    __shared__ float s_all[8][8][32];

    const int b    = blockIdx.x >> 1;                // bin
    const int half = blockIdx.x & 1;                 // replica half
    const int w    = threadIdx.x >> 5;
    const int lane = threadIdx.x & 31;

    // warp 0, lanes 0..15: exclusive prefix over this half's replica counts
    if (threadIdx.x < 32) {
        int c = 0;
        if (lane < HREP) {
            c = g_cnt32[b * NREP + half * HREP + lane];
            if (c > CAP32) c = CAP32;
        }
        int x = c;
        #pragma unroll
        for (int d = 1; d < HREP; d <<= 1) {
            int y = __shfl_up_sync(0xffffffffu, x, d);
            if (lane >= d) x += y;
        }
        if (lane < HREP) s_pref[lane + 1] = x;
        if (lane == 0)  s_pref[0] = 0;
    }
    __syncthreads();

    // cooperative compaction: replica regions -> contiguous smem list
    #pragma unroll
    for (int r = w; r < HREP; r += 8) {
        int base = s_pref[r];
        int c    = s_pref[r + 1] - base;
        const int4* src = g_rec32 + (b * NREP + half * HREP + r) * CAP32;
        for (int t = lane; t < c; t += 32) {
            int d = base + t;
            if (d < SCAP_H) s_rec[d] = __ldg(src + t);
        }
    }
    __syncthreads();

    int T = s_pref[HREP];
    if (T > SCAP_H) T = SCAP_H;

    // per-warp accumulation, feat loads pipelined 8 deep (stride 8 warps)
    float a0=0,a1=0,a2=0,a3=0,a4=0,a5=0,a6=0,a7=0;
    float F[8];
    #pragma unroll
    for (int t = 0; t < 8; t++) {
        int j = w + t * 8;
        F[t] = (j < T) ? __ldg(feat + s_rec[j].x * C + lane) : 0.f;
    }
    int k = 0;
    for (int j = w; j < T; j += 8, k++) {
        int t = k & 7;
        int4 rc = s_rec[j];                          // broadcast LDS.128
        float fc = F[t];
        int jn = j + 64;
        F[t] = (jn < T) ? __ldg(feat + s_rec[jn].x * C + lane) : 0.f;
        ACC(rc, fc);
    }

    // reduce 8 warps x 8 corners in smem, then one RED per lane per corner
    s_all[w][0][lane] = a0; s_all[w][1][lane] = a1;
    s_all[w][2][lane] = a2; s_all[w][3][lane] = a3;
    s_all[w][4][lane] = a4; s_all[w][5][lane] = a5;
    s_all[w][6][lane] = a6; s_all[w][7][lane] = a7;
    __syncthreads();

    float s = 0.f;
    #pragma unroll
    for (int q = 0; q < 8; q++) s += s_all[q][w][lane];
    int bx = b >> 6, by = (b >> 3) & 7, bz = b & 7;
    int cx = (bx + (w >> 2)) & 7;
    int cy = (by + ((w >> 1) & 1)) & 7;
    int cz = (bz + (w & 1)) & 7;
    atomicAdd(&g_img[((cx << 6) | (cy << 3) | cz) * C + lane], s);
}

// -------- periodic 3x3x3 conv: grid = 27 taps x 16 half-slabs --------
__global__ void conv_k(const float* __restrict__ kern, int stage) {
    const float* src = (stage == 0) ? g_img : (stage == 1) ? g_h1 : g_h2;
    float*       dst = (stage == 0) ? g_h1  : (stage == 1) ? g_t  : g_out;

    __shared__ float s_in[32 * 32];
    const int tid = threadIdx.x;
    const int o = tid & 31, w = tid >> 5;
    const int tap = blockIdx.x % 27;
    const int grp = blockIdx.x / 27;
    const int dx = tap / 9 - 1, dy = (tap / 3) % 3 - 1, dz = tap % 3 - 1;
    const int x = grp >> 1, yh = (grp & 1) << 2;
    const int sx = (x + dx) & 7;

    #pragma unroll
    for (int k = 0; k < 4; k++) {
        int lc = w * 4 + k;
        int y = yh + (lc >> 3), z = lc & 7;
        int scell = (sx << 6) | (((y + dy) & 7) << 3) | ((z + dz) & 7);
        s_in[lc * 32 + o] = __ldg(&src[scell * 32 + o]);
    }
    float4 kv[8];
    const float4* kp = reinterpret_cast<const float4*>(kern + (tap * 32 + o) * 32);
    #pragma unroll
    for (int i = 0; i < 8; i++) kv[i] = __ldg(&kp[i]);
    __syncthreads();

    float acc[4] = {0,0,0,0};
    #pragma unroll
    for (int i4 = 0; i4 < 8; i4++) {
        #pragma unroll
        for (int k = 0; k < 4; k++) {
            float4 sv = *reinterpret_cast<const float4*>(&s_in[(w * 4 + k) * 32 + i4 * 4]);
            acc[k] += sv.x * kv[i4].x + sv.y * kv[i4].y
                    + sv.z * kv[i4].z + sv.w * kv[i4].w;
        }
    }
    int base = (grp * 32 + w * 4) * 32 + o;
    #pragma unroll
    for (int k = 0; k < 4; k++)
        atomicAdd(&dst[base + k * 32], acc[k]);
}

// -------- residual + silu --------
__global__ void epi_k() {
    int j = blockIdx.x * 256 + threadIdx.x;
    if (j < NCELL * C) {
        float t = g_t[j];
        g_h2[j] = g_h1[j] + t * (1.f / (1.f + __expf(-t)));
    }
}

// -------- 2x2x2 periodic box-sum of decoder output --------
__global__ void box_k() {
    int j = blockIdx.x * 256 + threadIdx.x;
    if (j >= NCELL * C) return;
    int o = j & 31, cell = j >> 5;
    int x = cell >> 6, y = (cell >> 3) & 7, z = cell & 7;
    float s = 0.f;
    #pragma unroll
    for (int k = 0; k < 8; k++) {
        int cx = (x + (k >> 2)) & 7;
        int cy = (y + ((k >> 1) & 1)) & 7;
        int cz = (z + (k & 1)) & 7;
        s += g_out[(((cx << 6) | (cy << 3) | cz) << 5) + o];
    }
    g_B[j] = s;
}

// -------- gather: recompute cell from pos; fully coalesced --------
__global__ void gather_k(const float* __restrict__ pos, float* __restrict__ out, int N) {
    int wid  = blockIdx.x * 8 + (threadIdx.x >> 5);
    int lane = threadIdx.x & 31;
    int p0 = wid * 8;
    if (p0 >= N) return;

    float v = 0.f;
    int gi = p0 * 3 + lane;
    if (lane < 24 && gi < N * 3) v = __ldg(pos + gi);

    int k8 = lane & 7;
    float ax = __shfl_sync(0xffffffffu, v, 3 * k8);
    float ay = __shfl_sync(0xffffffffu, v, 3 * k8 + 1);
    float az = __shfl_sync(0xffffffffu, v, 3 * k8 + 2);
    int cell = ((((int)floorf(ax * 8.f)) & 7) << 6)
             | ((((int)floorf(ay * 8.f)) & 7) << 3)
             |  (((int)floorf(az * 8.f)) & 7);

    #pragma unroll
    for (int k = 0; k < 8; k++) {
        int ck = __shfl_sync(0xffffffffu, cell, k);
        float val = g_B[ck * 32 + lane];
        if (p0 + k < N) out[(p0 + k) * 32 + lane] = val;
    }
}

extern "C" void kernel_launch(void* const* d_in, const int* in_sizes, int n_in,
                              void* d_out, int out_size) {
    const float* pos  = (const float*)d_in[0];
    const float* feat = (const float*)d_in[1];
    const float* enc  = (const float*)d_in[2];
    const float* inn  = (const float*)d_in[3];
    const float* dec  = (const float*)d_in[4];
    float* out = (float*)d_out;
    int N = in_sizes[0] / 3;

    zero_k   <<<64, 256>>>();                          // idx 0
    bin_k    <<<(N + 255) / 256, 256>>>(pos, N);       // idx 1
    probe_k  <<<1, 32>>>();                            // idx 2
    scatter_k<<<NCELL * 2, 256>>>(feat);               // idx 3  <-- profiled slot
    conv_k   <<<432, 256>>>(enc, 0);                   // idx 4
    conv_k   <<<432, 256>>>(inn, 1);                   // idx 5
    epi_k    <<<64, 256>>>();                          // idx 6
    conv_k   <<<432, 256>>>(dec, 2);                   // idx 7
    box_k    <<<64, 256>>>();                          // idx 8
    gather_k <<<(N + 63) / 64, 256>>>(pos, out, N);    // idx 9
}

// round 8
// speedup vs baseline: 1.1647x; 1.1647x over previous
#include <cuda_runtime.h>
#include <math.h>

#define NCELL 512
#define C 32
#define NREP 32           // counter replicas per cell (replica = point_idx & 31)
#define CAP32 64          // slots per (cell, replica); mean ~30.5
#define SCAP 1280         // smem record capacity per bin; mean ~977, +9.7 sigma

// -------- static scratch (no cudaMalloc allowed) --------
__device__ int   g_cnt32[NCELL * NREP];
__device__ int4  g_rec32[NCELL * NREP * CAP32];   // {idx, fx, fy, fz}
__device__ float g_img[NCELL * C];
__device__ float g_h1 [NCELL * C];
__device__ float g_t  [NCELL * C];
__device__ float g_out[NCELL * C];
__device__ float g_B  [NCELL * C];
__device__ int   g_pad[32];

// -------- zero counters + accumulated buffers --------
__global__ void zero_k() {
    int j = blockIdx.x * 256 + threadIdx.x;          // 16384 threads
    g_cnt32[j] = 0;
    g_img[j] = 0.f; g_h1[j] = 0.f; g_t[j] = 0.f; g_out[j] = 0.f;
}

// -------- probes: shift bin_k into ncu's profiled slot (4th launch) --------
__global__ void probe_k() {
    if (threadIdx.x == 0) g_pad[0] = 1;
}

// -------- bin points: replicated counters kill atomic serialization --------
__global__ void bin_k(const float* __restrict__ pos, int N) {
    int p = blockIdx.x * 256 + threadIdx.x;
    if (p >= N) return;
    float sx = pos[3 * p + 0] * 8.f;
    float sy = pos[3 * p + 1] * 8.f;
    float sz = pos[3 * p + 2] * 8.f;
    float bx = floorf(sx), by = floorf(sy), bz = floorf(sz);
    int cell = ((((int)bx) & 7) << 6) | ((((int)by) & 7) << 3) | (((int)bz) & 7);
    int r = p & (NREP - 1);
    int slot = atomicAdd(&g_cnt32[cell * NREP + r], 1);
    if (slot < CAP32) {
        int4 rec;
        rec.x = p;
        rec.y = __float_as_int(sx - bx);
        rec.z = __float_as_int(sy - by);
        rec.w = __float_as_int(sz - bz);
        g_rec32[(cell * NREP + r) * CAP32 + slot] = rec;
    }
}

#define ACC(rc, fc) { \
    float fx = __int_as_float((rc).y), fy = __int_as_float((rc).z), fz = __int_as_float((rc).w); \
    float gx = 1.f - fx, gy = 1.f - fy, gz = 1.f - fz; \
    float w00 = gy * gz, w01 = gy * fz, w10 = fy * gz, w11 = fy * fz; \
    float p0 = gx * (fc), p1 = fx * (fc); \
    a0 += w00 * p0; a1 += w01 * p0; a2 += w10 * p0; a3 += w11 * p0; \
    a4 += w00 * p1; a5 += w01 * p1; a6 += w10 * p1; a7 += w11 * p1; }

// -------- scatter: CTA per bin, smem-staged records, 4-deep feat ring (R6 config) --------
__global__ void __launch_bounds__(256) scatter_k(const float* __restrict__ feat) {
    __shared__ int4  s_rec[SCAP];
    __shared__ int   s_pref[NREP + 1];
    __shared__ float s_all[8][8][32];

    const int b    = blockIdx.x;
    const int w    = threadIdx.x >> 5;
    const int lane = threadIdx.x & 31;

    // warp 0: exclusive prefix over the 32 replica counts
    if (threadIdx.x < 32) {
        int c = g_cnt32[b * NREP + lane];
        if (c > CAP32) c = CAP32;
        int x = c;
        #pragma unroll
        for (int d = 1; d < 32; d <<= 1) {
            int y = __shfl_up_sync(0xffffffffu, x, d);
            if (lane >= d) x += y;
        }
        s_pref[lane + 1] = x;
        if (lane == 0) s_pref[0] = 0;
    }
    __syncthreads();

    // cooperative compaction: replica regions -> contiguous smem list
    #pragma unroll
    for (int r = w; r < NREP; r += 8) {
        int base = s_pref[r];
        int c    = s_pref[r + 1] - base;
        const int4* src = g_rec32 + (b * NREP + r) * CAP32;
        for (int t = lane; t < c; t += 32) {
            int d = base + t;
            if (d < SCAP) s_rec[d] = __ldg(src + t);
        }
    }
    __syncthreads();

    int T = s_pref[NREP];
    if (T > SCAP) T = SCAP;

    // per-warp accumulation, feat loads pipelined 4 deep (stride 8 warps)
    float a0=0,a1=0,a2=0,a3=0,a4=0,a5=0,a6=0,a7=0;
    float F[4];
    #pragma unroll
    for (int t = 0; t < 4; t++) {
        int j = w + t * 8;
        F[t] = (j < T) ? __ldg(feat + s_rec[j].x * C + lane) : 0.f;
    }
    int k = 0;
    for (int j = w; j < T; j += 8, k++) {
        int t = k & 3;
        int4 rc = s_rec[j];                          // broadcast LDS.128
        float fc = F[t];
        int jn = j + 32;
        F[t] = (jn < T) ? __ldg(feat + s_rec[jn].x * C + lane) : 0.f;
        ACC(rc, fc);
    }

    // reduce 8 warps x 8 corners in smem, then one RED per lane per corner
    s_all[w][0][lane] = a0; s_all[w][1][lane] = a1;
    s_all[w][2][lane] = a2; s_all[w][3][lane] = a3;
    s_all[w][4][lane] = a4; s_all[w][5][lane] = a5;
    s_all[w][6][lane] = a6; s_all[w][7][lane] = a7;
    __syncthreads();

    float s = 0.f;
    #pragma unroll
    for (int q = 0; q < 8; q++) s += s_all[q][w][lane];
    int bx = b >> 6, by = (b >> 3) & 7, bz = b & 7;
    int cx = (bx + (w >> 2)) & 7;
    int cy = (by + ((w >> 1) & 1)) & 7;
    int cz = (bz + (w & 1)) & 7;
    atomicAdd(&g_img[((cx << 6) | (cy << 3) | cz) * C + lane], s);
}

// -------- periodic 3x3x3 conv: grid = 27 taps x 16 half-slabs --------
// stage 0: img->h1 (encoder); stage 1: h1->t (inner);
// stage 2: decoder, staging computes h2 = h1 + silu(t) on the fly
__global__ void conv_k(const float* __restrict__ kern, int stage) {
    const float* src = (stage == 0) ? g_img : g_h1;
    float*       dst = (stage == 0) ? g_h1  : (stage == 1) ? g_t : g_out;

    __shared__ float s_in[32 * 32];
    const int tid = threadIdx.x;
    const int o = tid & 31, w = tid >> 5;
    const int tap = blockIdx.x % 27;
    const int grp = blockIdx.x / 27;
    const int dx = tap / 9 - 1, dy = (tap / 3) % 3 - 1, dz = tap % 3 - 1;
    const int x = grp >> 1, yh = (grp & 1) << 2;
    const int sx = (x + dx) & 7;

    #pragma unroll
    for (int k = 0; k < 4; k++) {
        int lc = w * 4 + k;
        int y = yh + (lc >> 3), z = lc & 7;
        int si = ((sx << 6) | (((y + dy) & 7) << 3) | ((z + dz) & 7)) * 32 + o;
        float v;
        if (stage == 2) {
            float t = __ldg(&g_t[si]);
            v = __ldg(&g_h1[si]) + t * (1.f / (1.f + __expf(-t)));
        } else {
            v = __ldg(&src[si]);
        }
        s_in[lc * 32 + o] = v;
    }
    float4 kv[8];
    const float4* kp = reinterpret_cast<const float4*>(kern + (tap * 32 + o) * 32);
    #pragma unroll
    for (int i = 0; i < 8; i++) kv[i] = __ldg(&kp[i]);
    __syncthreads();

    float acc[4] = {0,0,0,0};
    #pragma unroll
    for (int i4 = 0; i4 < 8; i4++) {
        #pragma unroll
        for (int k = 0; k < 4; k++) {
            float4 sv = *reinterpret_cast<const float4*>(&s_in[(w * 4 + k) * 32 + i4 * 4]);
            acc[k] += sv.x * kv[i4].x + sv.y * kv[i4].y
                    + sv.z * kv[i4].z + sv.w * kv[i4].w;
        }
    }
    int base = (grp * 32 + w * 4) * 32 + o;
    #pragma unroll
    for (int k = 0; k < 4; k++)
        atomicAdd(&dst[base + k * 32], acc[k]);
}

// -------- 2x2x2 periodic box-sum of decoder output --------
__global__ void box_k() {
    int j = blockIdx.x * 256 + threadIdx.x;
    if (j >= NCELL * C) return;
    int o = j & 31, cell = j >> 5;
    int x = cell >> 6, y = (cell >> 3) & 7, z = cell & 7;
    float s = 0.f;
    #pragma unroll
    for (int k = 0; k < 8; k++) {
        int cx = (x + (k >> 2)) & 7;
        int cy = (y + ((k >> 1) & 1)) & 7;
        int cz = (z + (k & 1)) & 7;
        s += g_out[(((cx << 6) | (cy << 3) | cz) << 5) + o];
    }
    g_B[j] = s;
}

// -------- gather: recompute cell from pos; fully coalesced --------
__global__ void gather_k(const float* __restrict__ pos, float* __restrict__ out, int N) {
    int wid  = blockIdx.x * 8 + (threadIdx.x >> 5);
    int lane = threadIdx.x & 31;
    int p0 = wid * 8;
    if (p0 >= N) return;

    float v = 0.f;
    int gi = p0 * 3 + lane;
    if (lane < 24 && gi < N * 3) v = __ldg(pos + gi);

    int k8 = lane & 7;
    float ax = __shfl_sync(0xffffffffu, v, 3 * k8);
    float ay = __shfl_sync(0xffffffffu, v, 3 * k8 + 1);
    float az = __shfl_sync(0xffffffffu, v, 3 * k8 + 2);
    int cell = ((((int)floorf(ax * 8.f)) & 7) << 6)
             | ((((int)floorf(ay * 8.f)) & 7) << 3)
             |  (((int)floorf(az * 8.f)) & 7);

    #pragma unroll
    for (int k = 0; k < 8; k++) {
        int ck = __shfl_sync(0xffffffffu, cell, k);
        float val = g_B[ck * 32 + lane];
        if (p0 + k < N) out[(p0 + k) * 32 + lane] = val;
    }
}

extern "C" void kernel_launch(void* const* d_in, const int* in_sizes, int n_in,
                              void* d_out, int out_size) {
    const float* pos  = (const float*)d_in[0];
    const float* feat = (const float*)d_in[1];
    const float* enc  = (const float*)d_in[2];
    const float* inn  = (const float*)d_in[3];
    const float* dec  = (const float*)d_in[4];
    float* out = (float*)d_out;
    int N = in_sizes[0] / 3;

    zero_k   <<<64, 256>>>();                          // idx 0
    probe_k  <<<1, 32>>>();                            // idx 1
    probe_k  <<<1, 32>>>();                            // idx 2
    bin_k    <<<(N + 255) / 256, 256>>>(pos, N);       // idx 3  <-- profiled slot
    scatter_k<<<NCELL, 256>>>(feat);                   // idx 4
    conv_k   <<<432, 256>>>(enc, 0);                   // idx 5
    conv_k   <<<432, 256>>>(inn, 1);                   // idx 6
    conv_k   <<<432, 256>>>(dec, 2);                   // idx 7 (silu fused in staging)
    box_k    <<<64, 256>>>();                          // idx 8
    gather_k <<<(N + 63) / 64, 256>>>(pos, out, N);    // idx 9
}

// round 9
// speedup vs baseline: 1.3611x; 1.1687x over previous
#include <cuda_runtime.h>
#include <math.h>

#define NCELL 512
#define C 32
#define NREP 32           // counter replicas per cell (replica = point_idx & 31)
#define CAP32 64          // slots per (cell, replica); mean ~30.5
#define SCAP 1280         // smem record capacity per bin; mean ~977, +9.7 sigma

// -------- static scratch (no cudaMalloc allowed) --------
__device__ int   g_cnt32[NCELL * NREP];
__device__ int4  g_rec32[NCELL * NREP * CAP32];   // {idx, fx, fy, fz}
__device__ float g_img[NCELL * C];
__device__ float g_h1 [NCELL * C];
__device__ float g_t  [NCELL * C];
__device__ float g_out[NCELL * C];
__device__ float g_B  [NCELL * C];
__device__ int   g_pad[32];

// -------- zero counters + accumulated buffers --------
__global__ void zero_k() {
    int j = blockIdx.x * 256 + threadIdx.x;          // 16384 threads
    g_cnt32[j] = 0;
    g_img[j] = 0.f; g_h1[j] = 0.f; g_t[j] = 0.f; g_out[j] = 0.f;
}

// -------- probe: keeps scatter_k in ncu's profiled slot (4th launch) --------
__global__ void probe_k() {
    if (threadIdx.x == 0) g_pad[0] = 1;
}

// -------- bin points: replicated counters; 2 independent points per thread --------
__global__ void bin_k(const float* __restrict__ pos, int N) {
    int base = blockIdx.x * 512 + threadIdx.x;
    #pragma unroll
    for (int u = 0; u < 2; u++) {
        int p = base + u * 256;
        if (p < N) {
            float sx = pos[3 * p + 0] * 8.f;
            float sy = pos[3 * p + 1] * 8.f;
            float sz = pos[3 * p + 2] * 8.f;
            float bx = floorf(sx), by = floorf(sy), bz = floorf(sz);
            int cell = ((((int)bx) & 7) << 6) | ((((int)by) & 7) << 3) | (((int)bz) & 7);
            int r = p & (NREP - 1);
            int slot = atomicAdd(&g_cnt32[cell * NREP + r], 1);
            if (slot < CAP32) {
                int4 rec;
                rec.x = p;
                rec.y = __float_as_int(sx - bx);
                rec.z = __float_as_int(sy - by);
                rec.w = __float_as_int(sz - bz);
                g_rec32[(cell * NREP + r) * CAP32 + slot] = rec;
            }
        }
    }
}

#define ACC(rc, fc) { \
    float fx = __int_as_float((rc).y), fy = __int_as_float((rc).z), fz = __int_as_float((rc).w); \
    float gx = 1.f - fx, gy = 1.f - fy, gz = 1.f - fz; \
    float w00 = gy * gz, w01 = gy * fz, w10 = fy * gz, w11 = fy * fz; \
    float p0 = gx * (fc), p1 = fx * (fc); \
    a0 += w00 * p0; a1 += w01 * p0; a2 += w10 * p0; a3 += w11 * p0; \
    a4 += w00 * p1; a5 += w01 * p1; a6 += w10 * p1; a7 += w11 * p1; }

// -------- scatter: 1 CTA per bin, 16 warps, smem-staged records, 4-deep feat ring --------
__global__ void __launch_bounds__(512) scatter_k(const float* __restrict__ feat) {
    __shared__ int4  s_rec[SCAP];
    __shared__ int   s_pref[NREP + 1];
    __shared__ float s_all[16][8][32];

    const int b    = blockIdx.x;
    const int w    = threadIdx.x >> 5;               // 0..15
    const int lane = threadIdx.x & 31;

    // warp 0: exclusive prefix over the 32 replica counts
    if (threadIdx.x < 32) {
        int c = g_cnt32[b * NREP + lane];
        if (c > CAP32) c = CAP32;
        int x = c;
        #pragma unroll
        for (int d = 1; d < 32; d <<= 1) {
            int y = __shfl_up_sync(0xffffffffu, x, d);
            if (lane >= d) x += y;
        }
        s_pref[lane + 1] = x;
        if (lane == 0) s_pref[0] = 0;
    }
    __syncthreads();

    // cooperative compaction: replica regions -> contiguous smem list
    #pragma unroll
    for (int r = w; r < NREP; r += 16) {
        int base = s_pref[r];
        int c    = s_pref[r + 1] - base;
        const int4* src = g_rec32 + (b * NREP + r) * CAP32;
        for (int t = lane; t < c; t += 32) {
            int d = base + t;
            if (d < SCAP) s_rec[d] = __ldg(src + t);
        }
    }
    __syncthreads();

    int T = s_pref[NREP];
    if (T > SCAP) T = SCAP;

    // per-warp accumulation, feat loads pipelined 4 deep (stride 16 warps)
    float a0=0,a1=0,a2=0,a3=0,a4=0,a5=0,a6=0,a7=0;
    float F[4];
    #pragma unroll
    for (int t = 0; t < 4; t++) {
        int j = w + t * 16;
        F[t] = (j < T) ? __ldg(feat + s_rec[j].x * C + lane) : 0.f;
    }
    int k = 0;
    for (int j = w; j < T; j += 16, k++) {
        int t = k & 3;
        int4 rc = s_rec[j];                          // broadcast LDS.128
        float fc = F[t];
        int jn = j + 64;
        F[t] = (jn < T) ? __ldg(feat + s_rec[jn].x * C + lane) : 0.f;
        ACC(rc, fc);
    }

    // reduce 16 warps x 8 corners: warp w sums its half of sources for corner w&7
    s_all[w][0][lane] = a0; s_all[w][1][lane] = a1;
    s_all[w][2][lane] = a2; s_all[w][3][lane] = a3;
    s_all[w][4][lane] = a4; s_all[w][5][lane] = a5;
    s_all[w][6][lane] = a6; s_all[w][7][lane] = a7;
    __syncthreads();

    int cn = w & 7;
    int qb = (w >> 3) * 8;
    float s = 0.f;
    #pragma unroll
    for (int q = 0; q < 8; q++) s += s_all[qb + q][cn][lane];
    int bx = b >> 6, by = (b >> 3) & 7, bz = b & 7;
    int cx = (bx + (cn >> 2)) & 7;
    int cy = (by + ((cn >> 1) & 1)) & 7;
    int cz = (bz + (cn & 1)) & 7;
    atomicAdd(&g_img[((cx << 6) | (cy << 3) | cz) * C + lane], s);
}

// -------- periodic 3x3x3 conv: grid = 27 taps x 16 half-slabs --------
// stage 0: img->h1 (encoder); stage 1: h1->t (inner);
// stage 2: decoder, staging computes h2 = h1 + silu(t) on the fly
__global__ void conv_k(const float* __restrict__ kern, int stage) {
    const float* src = (stage == 0) ? g_img : g_h1;
    float*       dst = (stage == 0) ? g_h1  : (stage == 1) ? g_t : g_out;

    __shared__ float s_in[32 * 32];
    const int tid = threadIdx.x;
    const int o = tid & 31, w = tid >> 5;
    const int tap = blockIdx.x % 27;
    const int grp = blockIdx.x / 27;
    const int dx = tap / 9 - 1, dy = (tap / 3) % 3 - 1, dz = tap % 3 - 1;
    const int x = grp >> 1, yh = (grp & 1) << 2;
    const int sx = (x + dx) & 7;

    #pragma unroll
    for (int k = 0; k < 4; k++) {
        int lc = w * 4 + k;
        int y = yh + (lc >> 3), z = lc & 7;
        int si = ((sx << 6) | (((y + dy) & 7) << 3) | ((z + dz) & 7)) * 32 + o;
        float v;
        if (stage == 2) {
            float t = __ldg(&g_t[si]);
            v = __ldg(&g_h1[si]) + t * (1.f / (1.f + __expf(-t)));
        } else {
            v = __ldg(&src[si]);
        }
        s_in[lc * 32 + o] = v;
    }
    float4 kv[8];
    const float4* kp = reinterpret_cast<const float4*>(kern + (tap * 32 + o) * 32);
    #pragma unroll
    for (int i = 0; i < 8; i++) kv[i] = __ldg(&kp[i]);
    __syncthreads();

    float acc[4] = {0,0,0,0};
    #pragma unroll
    for (int i4 = 0; i4 < 8; i4++) {
        #pragma unroll
        for (int k = 0; k < 4; k++) {
            float4 sv = *reinterpret_cast<const float4*>(&s_in[(w * 4 + k) * 32 + i4 * 4]);
            acc[k] += sv.x * kv[i4].x + sv.y * kv[i4].y
                    + sv.z * kv[i4].z + sv.w * kv[i4].w;
        }
    }
    int base = (grp * 32 + w * 4) * 32 + o;
    #pragma unroll
    for (int k = 0; k < 4; k++)
        atomicAdd(&dst[base + k * 32], acc[k]);
}

// -------- 2x2x2 periodic box-sum of decoder output --------
__global__ void box_k() {
    int j = blockIdx.x * 256 + threadIdx.x;
    if (j >= NCELL * C) return;
    int o = j & 31, cell = j >> 5;
    int x = cell >> 6, y = (cell >> 3) & 7, z = cell & 7;
    float s = 0.f;
    #pragma unroll
    for (int k = 0; k < 8; k++) {
        int cx = (x + (k >> 2)) & 7;
        int cy = (y + ((k >> 1) & 1)) & 7;
        int cz = (z + (k & 1)) & 7;
        s += g_out[(((cx << 6) | (cy << 3) | cz) << 5) + o];
    }
    g_B[j] = s;
}

// -------- gather: recompute cell from pos; fully coalesced --------
__global__ void gather_k(const float* __restrict__ pos, float* __restrict__ out, int N) {
    int wid  = blockIdx.x * 8 + (threadIdx.x >> 5);
    int lane = threadIdx.x & 31;
    int p0 = wid * 8;
    if (p0 >= N) return;

    float v = 0.f;
    int gi = p0 * 3 + lane;
    if (lane < 24 && gi < N * 3) v = __ldg(pos + gi);

    int k8 = lane & 7;
    float ax = __shfl_sync(0xffffffffu, v, 3 * k8);
    float ay = __shfl_sync(0xffffffffu, v, 3 * k8 + 1);
    float az = __shfl_sync(0xffffffffu, v, 3 * k8 + 2);
    int cell = ((((int)floorf(ax * 8.f)) & 7) << 6)
             | ((((int)floorf(ay * 8.f)) & 7) << 3)
             |  (((int)floorf(az * 8.f)) & 7);

    #pragma unroll
    for (int k = 0; k < 8; k++) {
        int ck = __shfl_sync(0xffffffffu, cell, k);
        float val = g_B[ck * 32 + lane];
        if (p0 + k < N) out[(p0 + k) * 32 + lane] = val;
    }
}

extern "C" void kernel_launch(void* const* d_in, const int* in_sizes, int n_in,
                              void* d_out, int out_size) {
    const float* pos  = (const float*)d_in[0];
    const float* feat = (const float*)d_in[1];
    const float* enc  = (const float*)d_in[2];
    const float* inn  = (const float*)d_in[3];
    const float* dec  = (const float*)d_in[4];
    float* out = (float*)d_out;
    int N = in_sizes[0] / 3;

    zero_k   <<<64, 256>>>();                          // idx 0
    probe_k  <<<1, 32>>>();                            // idx 1
    bin_k    <<<(N + 511) / 512, 256>>>(pos, N);       // idx 2
    scatter_k<<<NCELL, 512>>>(feat);                   // idx 3  <-- profiled slot
    conv_k   <<<432, 256>>>(enc, 0);                   // idx 4
    conv_k   <<<432, 256>>>(inn, 1);                   // idx 5
    conv_k   <<<432, 256>>>(dec, 2);                   // idx 6 (silu fused in staging)
    box_k    <<<64, 256>>>();                          // idx 7
    gather_k <<<(N + 63) / 64, 256>>>(pos, out, N);    // idx 8
}